// round 11
// baseline (speedup 1.0000x reference)
#include <cuda_runtime.h>
#include <cuda_fp16.h>
#include <cstdint>

#define HW_ 256
#define C_  32
#define O_  32
#define B_  8

// byte offsets into dynamic smem
#define BIAS_B 0
#define DWS_B  128
#define GS_B   1280
#define A_B    2560                  // 512B aligned; 3*258 rows x 64B (swizzled)
#define A_SZ   (3*258*64)            // 49536
#define B_B    52224                 // 1024B aligned; 18 blocks x 1KB (swizzled)
#define SM_TOT_BYTES (B_B + 18*1024) // 70656 -> 3 CTAs/SM

#define STG_STRIDE 36                // epilogue staging o-stride (words)

// 512B-period XOR swizzle: bits {4,5} ^= bits {7,8}
#define SWZ(a) ((a) ^ ((((a) >> 7) & 3u) << 4))

__device__ __forceinline__ uint32_t smem_u32(const void* p) {
    uint32_t a;
    asm("{ .reg .u64 t; cvta.to.shared.u64 t, %1; cvt.u32.u64 %0, t; }" : "=r"(a) : "l"(p));
    return a;
}

__device__ __forceinline__ uint32_t pk2h(float a, float b) {
    __half2 h = __floats2half2_rn(a, b);
    return *reinterpret_cast<uint32_t*>(&h);
}

__device__ __forceinline__ void ldsm4(uint32_t& r0, uint32_t& r1, uint32_t& r2, uint32_t& r3,
                                      uint32_t addr) {
    asm volatile("ldmatrix.sync.aligned.m8n8.x4.shared.b16 {%0,%1,%2,%3}, [%4];"
                 : "=r"(r0), "=r"(r1), "=r"(r2), "=r"(r3) : "r"(addr));
}

__device__ __forceinline__ void mma16816(float* c, uint32_t a0, uint32_t a1,
                                         uint32_t a2, uint32_t a3,
                                         uint32_t b0, uint32_t b1) {
    asm volatile(
        "mma.sync.aligned.m16n8k16.row.col.f32.f16.f16.f32 "
        "{%0,%1,%2,%3}, {%4,%5,%6,%7}, {%8,%9}, {%0,%1,%2,%3};"
        : "+f"(c[0]), "+f"(c[1]), "+f"(c[2]), "+f"(c[3])
        : "r"(a0), "r"(a1), "r"(a2), "r"(a3), "r"(b0), "r"(b1));
}

__global__ __launch_bounds__(256, 3)
void dynamiconv_kernel(const float* __restrict__ x, const float* __restrict__ weight,
                       const float* __restrict__ dweight, const float* __restrict__ bias,
                       float* __restrict__ out)
{
    extern __shared__ char smraw[];
    float* bias_s = (float*)(smraw + BIAS_B);
    float* dws_s  = (float*)(smraw + DWS_B);
    float* gs     = (float*)(smraw + GS_B);

    const int tid  = threadIdx.x;
    const int lane = tid & 31;
    const int warp = tid >> 5;           // 0..7
    const int y = blockIdx.x;
    const int b = blockIdx.y;

    if (tid < 32) bias_s[tid] = bias[tid];
    for (int i = tid; i < 288; i += 256) dws_s[i] = dweight[i];

    // ---- B fill: thread owns contiguous 36-float weight chunk; swizzled STS ----
    {
        float wchunk[36];
        const float4* ws4 = (const float4*)(weight + tid * 36);
        #pragma unroll
        for (int j = 0; j < 9; j++) ((float4*)wchunk)[j] = ws4[j];
        const int o    = tid >> 3;
        const int kpg0 = (tid & 7) * 2;
        const int kch0 = kpg0 >> 3, kp0 = kpg0 & 7;
        const int kpg1 = kpg0 + 1;
        const int kch1 = kpg1 >> 3, kp1 = kpg1 & 7;
        #pragma unroll
        for (int tap = 0; tap < 9; tap++) {
            uint32_t off0 = B_B + (uint32_t)(tap*2 + kch0)*1024 + o*32 + kp0*4;
            uint32_t off1 = B_B + (uint32_t)(tap*2 + kch1)*1024 + o*32 + kp1*4;
            *(uint32_t*)(smraw + SWZ(off0)) = pk2h(wchunk[tap],      wchunk[tap + 9]);
            *(uint32_t*)(smraw + SWZ(off1)) = pk2h(wchunk[tap + 18], wchunk[tap + 27]);
        }
    }

    // ---- A fill: thread = pixel (hp = tid+1); swizzled 64B rows ----
    const float* xb = x + (size_t)b * C_ * HW_ * HW_;
    {
        const int gx = tid;
        #pragma unroll
        for (int r = 0; r < 3; r++) {
            int gy = y - 1 + r;
            bool inb = ((unsigned)gy < (unsigned)HW_);
            const float* src = xb + (size_t)gy * HW_ + gx;
            uint32_t rowoff = A_B + (uint32_t)(r * 258 + gx + 1) * 64;
            #pragma unroll
            for (int q = 0; q < 4; q++) {
                float v[8];
                #pragma unroll
                for (int j = 0; j < 8; j++)
                    v[j] = inb ? src[(size_t)(8*q + j) * (HW_*HW_)] : 0.f;
                uint4 w = make_uint4(pk2h(v[0], v[1]), pk2h(v[2], v[3]),
                                     pk2h(v[4], v[5]), pk2h(v[6], v[7]));
                *(uint4*)(smraw + SWZ(rowoff + q * 16)) = w;
            }
        }
        if (tid < 24) {
            int r = tid >> 3, rem = tid & 7, e = rem >> 2, q = rem & 3;
            uint32_t rowoff = A_B + (uint32_t)(r * 258 + e * 257) * 64;
            *(uint4*)(smraw + SWZ(rowoff + q * 16)) = make_uint4(0, 0, 0, 0);
        }
    }
    __syncthreads();

    const int pxw = warp * 32;

    // ================= gate pass (lane = channel; transpose-reduce) =================
    {
        const int c = lane;
        const int sh = (lane & 1) * 16;
        const uint32_t cw = (uint32_t)(c >> 1) * 4;
        float dwr[9], sd2 = 0.f;
        #pragma unroll
        for (int j = 0; j < 9; j++) { dwr[j] = 0.5f * dws_s[c * 9 + j]; sd2 += dwr[j]; }

        float c0[3], c1[3];
        #pragma unroll
        for (int r = 0; r < 3; r++) {
            uint32_t w0 = *(const uint32_t*)(smraw + SWZ(A_B + (uint32_t)(r*258 + pxw)     * 64 + cw));
            uint32_t w1 = *(const uint32_t*)(smraw + SWZ(A_B + (uint32_t)(r*258 + pxw + 1) * 64 + cw));
            float v0 = __half2float(__ushort_as_half((unsigned short)(w0 >> sh)));
            float v1 = __half2float(__ushort_as_half((unsigned short)(w1 >> sh)));
            asm("tanh.approx.f32 %0, %1;" : "=f"(c0[r]) : "f"(v0 * 0.5f));
            asm("tanh.approx.f32 %0, %1;" : "=f"(c1[r]) : "f"(v1 * 0.5f));
        }
        float v[16];
        #pragma unroll
        for (int px = 0; px < 32; px++) {
            float c2[3];
            #pragma unroll
            for (int r = 0; r < 3; r++) {
                uint32_t w = *(const uint32_t*)(smraw + SWZ(A_B + (uint32_t)(r*258 + pxw + px + 2) * 64 + cw));
                float vv = __half2float(__ushort_as_half((unsigned short)(w >> sh)));
                asm("tanh.approx.f32 %0, %1;" : "=f"(c2[r]) : "f"(vv * 0.5f));
            }
            float p = sd2;
            #pragma unroll
            for (int r = 0; r < 3; r++) {
                p = fmaf(dwr[r * 3 + 0], c0[r], p);
                p = fmaf(dwr[r * 3 + 1], c1[r], p);
                p = fmaf(dwr[r * 3 + 2], c2[r], p);
            }
            v[px & 15] = p;
            #pragma unroll
            for (int r = 0; r < 3; r++) { c0[r] = c1[r]; c1[r] = c2[r]; }

            if ((px & 15) == 15) {
                #pragma unroll
                for (int i = 0; i < 16; i++)
                    v[i] += __shfl_xor_sync(0xFFFFFFFFu, v[i], 16);
                #pragma unroll
                for (int i = 0; i < 8; i++) {
                    float snd = (lane & 8) ? v[i] : v[i+8];
                    float kpv = (lane & 8) ? v[i+8] : v[i];
                    v[i] = kpv + __shfl_xor_sync(0xFFFFFFFFu, snd, 8);
                }
                #pragma unroll
                for (int i = 0; i < 4; i++) {
                    float snd = (lane & 4) ? v[i] : v[i+4];
                    float kpv = (lane & 4) ? v[i+4] : v[i];
                    v[i] = kpv + __shfl_xor_sync(0xFFFFFFFFu, snd, 4);
                }
                #pragma unroll
                for (int i = 0; i < 2; i++) {
                    float snd = (lane & 2) ? v[i] : v[i+2];
                    float kpv = (lane & 2) ? v[i+2] : v[i];
                    v[i] = kpv + __shfl_xor_sync(0xFFFFFFFFu, snd, 2);
                }
                {
                    float snd = (lane & 1) ? v[0] : v[1];
                    float kpv = (lane & 1) ? v[1] : v[0];
                    v[0] = kpv + __shfl_xor_sync(0xFFFFFFFFu, snd, 1);
                }
                if (lane < 16) gs[pxw + (px & ~15) + lane] = v[0];
            }
        }
    }
    __syncthreads();

    // ================= mainloop: swizzled ldmatrix + mma (fp16) =================
    const uint32_t sbase = smem_u32(smraw);
    const uint32_t laneArow = ((lane >> 3) & 1) * 8 + (lane & 7);
    const uint32_t laneAk   = (lane >> 4) * 16;
    const uint32_t laneBrow = ((lane >> 4) & 1) * 8 + (lane & 7);
    const uint32_t laneBk   = ((lane >> 3) & 1) * 16;

    float acc[2][4][4];
    #pragma unroll
    for (int mb = 0; mb < 2; mb++)
        #pragma unroll
        for (int nb = 0; nb < 4; nb++)
            #pragma unroll
            for (int r = 0; r < 4; r++) acc[mb][nb][r] = 0.0f;

    #pragma unroll 1
    for (int ki = 0; ki < 3; ki++) {
        #pragma unroll 1
        for (int kj = 0; kj < 3; kj++) {
            uint32_t araw = A_B + (uint32_t)(ki*258 + pxw + kj + laneArow) * 64 + laneAk;
            uint32_t braw = B_B + (uint32_t)((ki*3 + kj) * 2) * 1024 + laneBrow * 32 + laneBk;
            uint32_t a0[8], a1[8], b0q[8], b1q[8];
            ldsm4(a0[0], a0[1], a0[2], a0[3], sbase + SWZ(araw));
            ldsm4(a0[4], a0[5], a0[6], a0[7], sbase + SWZ(araw + 1024));
            ldsm4(b0q[0], b0q[1], b0q[2], b0q[3], sbase + SWZ(braw));
            ldsm4(b0q[4], b0q[5], b0q[6], b0q[7], sbase + SWZ(braw + 512));
            ldsm4(a1[0], a1[1], a1[2], a1[3], sbase + SWZ(araw + 32));
            ldsm4(a1[4], a1[5], a1[6], a1[7], sbase + SWZ(araw + 32 + 1024));
            ldsm4(b1q[0], b1q[1], b1q[2], b1q[3], sbase + SWZ(braw + 1024));
            ldsm4(b1q[4], b1q[5], b1q[6], b1q[7], sbase + SWZ(braw + 1024 + 512));
            #pragma unroll
            for (int mb = 0; mb < 2; mb++) {
                #pragma unroll
                for (int nb = 0; nb < 4; nb++)
                    mma16816(acc[mb][nb], a0[mb*4+0], a0[mb*4+1], a0[mb*4+2], a0[mb*4+3],
                             b0q[2*nb], b0q[2*nb+1]);
                #pragma unroll
                for (int nb = 0; nb < 4; nb++)
                    mma16816(acc[mb][nb], a1[mb*4+0], a1[mb*4+1], a1[mb*4+2], a1[mb*4+3],
                             b1q[2*nb], b1q[2*nb+1]);
            }
        }
    }

    // ================= epilogue: gate*acc + bias, smem transpose, STG.128 =================
    const int tig = lane & 3, grp = lane >> 2;
    __syncthreads();     // all warps done reading A before staging overwrites it

    float* st = (float*)(smraw + A_B) + warp * (32 * STG_STRIDE);
    #pragma unroll
    for (int mb = 0; mb < 2; mb++) {
        int pxl = mb * 16 + grp;
        float g0 = gs[pxw + pxl], g1 = gs[pxw + pxl + 8];
        #pragma unroll
        for (int nb = 0; nb < 4; nb++) {
            int o = nb * 8 + tig * 2;
            float bi0 = bias_s[o], bi1 = bias_s[o + 1];
            st[o       * STG_STRIDE + pxl]     = fmaf(g0, acc[mb][nb][0], bi0);
            st[(o + 1) * STG_STRIDE + pxl]     = fmaf(g0, acc[mb][nb][1], bi1);
            st[o       * STG_STRIDE + pxl + 8] = fmaf(g1, acc[mb][nb][2], bi0);
            st[(o + 1) * STG_STRIDE + pxl + 8] = fmaf(g1, acc[mb][nb][3], bi1);
        }
    }
    __syncwarp();

    {
        const int g = lane >> 3, i = lane & 7;
        float* ob = out + (size_t)b * O_ * HW_ * HW_ + (size_t)y * HW_ + pxw;
        #pragma unroll
        for (int it = 0; it < 8; it++) {
            int o = it * 4 + g;
            float4 v = *(const float4*)(st + o * STG_STRIDE + i * 4);
            *(float4*)(ob + (size_t)o * (HW_*HW_) + i * 4) = v;
        }
    }
}

extern "C" void kernel_launch(void* const* d_in, const int* in_sizes, int n_in,
                              void* d_out, int out_size)
{
    const float* x       = (const float*)d_in[0];
    const float* weight  = (const float*)d_in[1];
    const float* dweight = (const float*)d_in[2];
    const float* bias    = (const float*)d_in[3];
    float* out = (float*)d_out;

    cudaFuncSetAttribute(dynamiconv_kernel,
                         cudaFuncAttributeMaxDynamicSharedMemorySize, SM_TOT_BYTES);

    dim3 grid(HW_, B_, 1);   // 256 rows x 8 batches = 2048 CTAs
    dynamiconv_kernel<<<grid, 256, SM_TOT_BYTES>>>(x, weight, dweight, bias, out);
}

// round 12
// speedup vs baseline: 1.1499x; 1.1499x over previous
#include <cuda_runtime.h>
#include <cuda_fp16.h>
#include <cstdint>

#define HW_ 256
#define C_  32
#define O_  32
#define B_  8

// byte offsets into dynamic smem
#define BIAS_B 0
#define DWS_B  128
#define GS_B   1280
#define A_B    2560                  // 512B aligned; 3*258 rows x 64B (swizzled)
#define B_B    52224                 // 512B aligned; 18 blocks x 1KB (swizzled)
#define SM_TOT_BYTES (B_B + 18*1024) // 70656 -> 3 CTAs/SM

#define STG_STRIDE 36                // epilogue staging o-stride (words)

// 512B-period XOR swizzle: bits {4,5} ^= bits {7,8}
#define SWZ(a) ((a) ^ ((((a) >> 7) & 3u) << 4))

// pre-packed, pre-swizzled B smem image (identical for every CTA)
__device__ uint32_t g_Bimg[4608];

__device__ __forceinline__ uint32_t smem_u32(const void* p) {
    uint32_t a;
    asm("{ .reg .u64 t; cvta.to.shared.u64 t, %1; cvt.u32.u64 %0, t; }" : "=r"(a) : "l"(p));
    return a;
}

__device__ __forceinline__ uint32_t pk2h(float a, float b) {
    __half2 h = __floats2half2_rn(a, b);
    return *reinterpret_cast<uint32_t*>(&h);
}

__device__ __forceinline__ void ldsm4(uint32_t& r0, uint32_t& r1, uint32_t& r2, uint32_t& r3,
                                      uint32_t addr) {
    asm volatile("ldmatrix.sync.aligned.m8n8.x4.shared.b16 {%0,%1,%2,%3}, [%4];"
                 : "=r"(r0), "=r"(r1), "=r"(r2), "=r"(r3) : "r"(addr));
}

__device__ __forceinline__ void mma16816(float* c, uint32_t a0, uint32_t a1,
                                         uint32_t a2, uint32_t a3,
                                         uint32_t b0, uint32_t b1) {
    asm volatile(
        "mma.sync.aligned.m16n8k16.row.col.f32.f16.f16.f32 "
        "{%0,%1,%2,%3}, {%4,%5,%6,%7}, {%8,%9}, {%0,%1,%2,%3};"
        : "+f"(c[0]), "+f"(c[1]), "+f"(c[2]), "+f"(c[3])
        : "r"(a0), "r"(a1), "r"(a2), "r"(a3), "r"(b0), "r"(b1));
}

// ---------------- prepack kernel: build swizzled B image once ----------------
__global__ void prepack_kernel(const float* __restrict__ weight)
{
    const int tid = threadIdx.x;   // 256 threads
    float wchunk[36];
    const float4* ws4 = (const float4*)(weight + tid * 36);
    #pragma unroll
    for (int j = 0; j < 9; j++) ((float4*)wchunk)[j] = ws4[j];
    const int o    = tid >> 3;
    const int kpg0 = (tid & 7) * 2;
    const int kch0 = kpg0 >> 3, kp0 = kpg0 & 7;
    const int kpg1 = kpg0 + 1;
    const int kch1 = kpg1 >> 3, kp1 = kpg1 & 7;
    #pragma unroll
    for (int tap = 0; tap < 9; tap++) {
        uint32_t rel0 = (uint32_t)(tap*2 + kch0)*1024 + o*32 + kp0*4;
        uint32_t rel1 = (uint32_t)(tap*2 + kch1)*1024 + o*32 + kp1*4;
        g_Bimg[SWZ(rel0) >> 2] = pk2h(wchunk[tap],      wchunk[tap + 9]);
        g_Bimg[SWZ(rel1) >> 2] = pk2h(wchunk[tap + 18], wchunk[tap + 27]);
    }
}

// ---------------- main kernel ----------------
__global__ __launch_bounds__(256, 3)
void dynamiconv_kernel(const float* __restrict__ x,
                       const float* __restrict__ dweight, const float* __restrict__ bias,
                       float* __restrict__ out)
{
    extern __shared__ char smraw[];
    float* bias_s = (float*)(smraw + BIAS_B);
    float* dws_s  = (float*)(smraw + DWS_B);
    float* gs     = (float*)(smraw + GS_B);

    const int tid  = threadIdx.x;
    const int lane = tid & 31;
    const int warp = tid >> 5;           // 0..7
    const int y = blockIdx.x;
    const int b = blockIdx.y;

    if (tid < 32) bias_s[tid] = bias[tid];
    for (int i = tid; i < 288; i += 256) dws_s[i] = dweight[i];

    // ---- B fill: linear copy of pre-swizzled image (coalesced) ----
    {
        const uint4* src = (const uint4*)g_Bimg;
        uint4* dst = (uint4*)(smraw + B_B);
        #pragma unroll
        for (int i = tid; i < 1152; i += 256) dst[i] = src[i];
    }

    // ---- A fill: thread = pixel (hp = tid+1); swizzled 64B rows ----
    const float* xb = x + (size_t)b * C_ * HW_ * HW_;
    {
        const int gx = tid;
        #pragma unroll
        for (int r = 0; r < 3; r++) {
            int gy = y - 1 + r;
            bool inb = ((unsigned)gy < (unsigned)HW_);
            const float* src = xb + (size_t)gy * HW_ + gx;
            uint32_t rowoff = A_B + (uint32_t)(r * 258 + gx + 1) * 64;
            #pragma unroll
            for (int q = 0; q < 4; q++) {
                float v[8];
                #pragma unroll
                for (int j = 0; j < 8; j++)
                    v[j] = inb ? src[(size_t)(8*q + j) * (HW_*HW_)] : 0.f;
                uint4 w = make_uint4(pk2h(v[0], v[1]), pk2h(v[2], v[3]),
                                     pk2h(v[4], v[5]), pk2h(v[6], v[7]));
                *(uint4*)(smraw + SWZ(rowoff + q * 16)) = w;
            }
        }
        if (tid < 24) {
            int r = tid >> 3, rem = tid & 7, e = rem >> 2, q = rem & 3;
            uint32_t rowoff = A_B + (uint32_t)(r * 258 + e * 257) * 64;
            *(uint4*)(smraw + SWZ(rowoff + q * 16)) = make_uint4(0, 0, 0, 0);
        }
    }
    __syncthreads();

    const int pxw = warp * 32;

    // ================= gate pass (lane = channel; transpose-reduce) =================
    {
        const int c = lane;
        const int sh = (lane & 1) * 16;
        const uint32_t cw = (uint32_t)(c >> 1) * 4;
        float dwr[9], sd2 = 0.f;
        #pragma unroll
        for (int j = 0; j < 9; j++) { dwr[j] = 0.5f * dws_s[c * 9 + j]; sd2 += dwr[j]; }

        float c0[3], c1[3];
        #pragma unroll
        for (int r = 0; r < 3; r++) {
            uint32_t w0 = *(const uint32_t*)(smraw + SWZ(A_B + (uint32_t)(r*258 + pxw)     * 64 + cw));
            uint32_t w1 = *(const uint32_t*)(smraw + SWZ(A_B + (uint32_t)(r*258 + pxw + 1) * 64 + cw));
            float v0 = __half2float(__ushort_as_half((unsigned short)(w0 >> sh)));
            float v1 = __half2float(__ushort_as_half((unsigned short)(w1 >> sh)));
            asm("tanh.approx.f32 %0, %1;" : "=f"(c0[r]) : "f"(v0 * 0.5f));
            asm("tanh.approx.f32 %0, %1;" : "=f"(c1[r]) : "f"(v1 * 0.5f));
        }
        float v[16];
        #pragma unroll
        for (int px = 0; px < 32; px++) {
            float c2[3];
            #pragma unroll
            for (int r = 0; r < 3; r++) {
                uint32_t w = *(const uint32_t*)(smraw + SWZ(A_B + (uint32_t)(r*258 + pxw + px + 2) * 64 + cw));
                float vv = __half2float(__ushort_as_half((unsigned short)(w >> sh)));
                asm("tanh.approx.f32 %0, %1;" : "=f"(c2[r]) : "f"(vv * 0.5f));
            }
            float p = sd2;
            #pragma unroll
            for (int r = 0; r < 3; r++) {
                p = fmaf(dwr[r * 3 + 0], c0[r], p);
                p = fmaf(dwr[r * 3 + 1], c1[r], p);
                p = fmaf(dwr[r * 3 + 2], c2[r], p);
            }
            v[px & 15] = p;
            #pragma unroll
            for (int r = 0; r < 3; r++) { c0[r] = c1[r]; c1[r] = c2[r]; }

            if ((px & 15) == 15) {
                #pragma unroll
                for (int i = 0; i < 16; i++)
                    v[i] += __shfl_xor_sync(0xFFFFFFFFu, v[i], 16);
                #pragma unroll
                for (int i = 0; i < 8; i++) {
                    float snd = (lane & 8) ? v[i] : v[i+8];
                    float kpv = (lane & 8) ? v[i+8] : v[i];
                    v[i] = kpv + __shfl_xor_sync(0xFFFFFFFFu, snd, 8);
                }
                #pragma unroll
                for (int i = 0; i < 4; i++) {
                    float snd = (lane & 4) ? v[i] : v[i+4];
                    float kpv = (lane & 4) ? v[i+4] : v[i];
                    v[i] = kpv + __shfl_xor_sync(0xFFFFFFFFu, snd, 4);
                }
                #pragma unroll
                for (int i = 0; i < 2; i++) {
                    float snd = (lane & 2) ? v[i] : v[i+2];
                    float kpv = (lane & 2) ? v[i+2] : v[i];
                    v[i] = kpv + __shfl_xor_sync(0xFFFFFFFFu, snd, 2);
                }
                {
                    float snd = (lane & 1) ? v[0] : v[1];
                    float kpv = (lane & 1) ? v[1] : v[0];
                    v[0] = kpv + __shfl_xor_sync(0xFFFFFFFFu, snd, 1);
                }
                if (lane < 16) gs[pxw + (px & ~15) + lane] = v[0];
            }
        }
    }
    __syncthreads();

    // ================= mainloop: swizzled ldmatrix + mma (fp16) =================
    const uint32_t sbase = smem_u32(smraw);
    const uint32_t laneArow = ((lane >> 3) & 1) * 8 + (lane & 7);
    const uint32_t laneAk   = (lane >> 4) * 16;
    const uint32_t laneBrow = ((lane >> 4) & 1) * 8 + (lane & 7);
    const uint32_t laneBk   = ((lane >> 3) & 1) * 16;

    float acc[2][4][4];
    #pragma unroll
    for (int mb = 0; mb < 2; mb++)
        #pragma unroll
        for (int nb = 0; nb < 4; nb++)
            #pragma unroll
            for (int r = 0; r < 4; r++) acc[mb][nb][r] = 0.0f;

    #pragma unroll 1
    for (int ki = 0; ki < 3; ki++) {
        #pragma unroll 1
        for (int kj = 0; kj < 3; kj++) {
            uint32_t araw = A_B + (uint32_t)(ki*258 + pxw + kj + laneArow) * 64 + laneAk;
            uint32_t braw = B_B + (uint32_t)((ki*3 + kj) * 2) * 1024 + laneBrow * 32 + laneBk;
            uint32_t a0[8], a1[8], b0q[8], b1q[8];
            ldsm4(a0[0], a0[1], a0[2], a0[3], sbase + SWZ(araw));
            ldsm4(a0[4], a0[5], a0[6], a0[7], sbase + SWZ(araw + 1024));
            ldsm4(b0q[0], b0q[1], b0q[2], b0q[3], sbase + SWZ(braw));
            ldsm4(b0q[4], b0q[5], b0q[6], b0q[7], sbase + SWZ(braw + 512));
            ldsm4(a1[0], a1[1], a1[2], a1[3], sbase + SWZ(araw + 32));
            ldsm4(a1[4], a1[5], a1[6], a1[7], sbase + SWZ(araw + 32 + 1024));
            ldsm4(b1q[0], b1q[1], b1q[2], b1q[3], sbase + SWZ(braw + 1024));
            ldsm4(b1q[4], b1q[5], b1q[6], b1q[7], sbase + SWZ(braw + 1024 + 512));
            #pragma unroll
            for (int mb = 0; mb < 2; mb++) {
                #pragma unroll
                for (int nb = 0; nb < 4; nb++)
                    mma16816(acc[mb][nb], a0[mb*4+0], a0[mb*4+1], a0[mb*4+2], a0[mb*4+3],
                             b0q[2*nb], b0q[2*nb+1]);
                #pragma unroll
                for (int nb = 0; nb < 4; nb++)
                    mma16816(acc[mb][nb], a1[mb*4+0], a1[mb*4+1], a1[mb*4+2], a1[mb*4+3],
                             b1q[2*nb], b1q[2*nb+1]);
            }
        }
    }

    // ================= epilogue: gate*acc + bias, smem transpose, STG.128 =================
    const int tig = lane & 3, grp = lane >> 2;
    __syncthreads();     // all warps done reading A before staging overwrites it

    float* st = (float*)(smraw + A_B) + warp * (32 * STG_STRIDE);
    #pragma unroll
    for (int mb = 0; mb < 2; mb++) {
        int pxl = mb * 16 + grp;
        float g0 = gs[pxw + pxl], g1 = gs[pxw + pxl + 8];
        #pragma unroll
        for (int nb = 0; nb < 4; nb++) {
            int o = nb * 8 + tig * 2;
            float bi0 = bias_s[o], bi1 = bias_s[o + 1];
            st[o       * STG_STRIDE + pxl]     = fmaf(g0, acc[mb][nb][0], bi0);
            st[(o + 1) * STG_STRIDE + pxl]     = fmaf(g0, acc[mb][nb][1], bi1);
            st[o       * STG_STRIDE + pxl + 8] = fmaf(g1, acc[mb][nb][2], bi0);
            st[(o + 1) * STG_STRIDE + pxl + 8] = fmaf(g1, acc[mb][nb][3], bi1);
        }
    }
    __syncwarp();

    {
        const int g = lane >> 3, i = lane & 7;
        float* ob = out + (size_t)b * O_ * HW_ * HW_ + (size_t)y * HW_ + pxw;
        #pragma unroll
        for (int it = 0; it < 8; it++) {
            int o = it * 4 + g;
            float4 v = *(const float4*)(st + o * STG_STRIDE + i * 4);
            *(float4*)(ob + (size_t)o * (HW_*HW_) + i * 4) = v;
        }
    }
}

extern "C" void kernel_launch(void* const* d_in, const int* in_sizes, int n_in,
                              void* d_out, int out_size)
{
    const float* x       = (const float*)d_in[0];
    const float* weight  = (const float*)d_in[1];
    const float* dweight = (const float*)d_in[2];
    const float* bias    = (const float*)d_in[3];
    float* out = (float*)d_out;

    cudaFuncSetAttribute(dynamiconv_kernel,
                         cudaFuncAttributeMaxDynamicSharedMemorySize, SM_TOT_BYTES);

    prepack_kernel<<<1, 256>>>(weight);

    dim3 grid(HW_, B_, 1);   // 256 rows x 8 batches = 2048 CTAs
    dynamiconv_kernel<<<grid, 256, SM_TOT_BYTES>>>(x, dweight, bias, out);
}

// round 15
// speedup vs baseline: 1.1848x; 1.0304x over previous
#include <cuda_runtime.h>
#include <cuda_fp16.h>
#include <cstdint>

#define HW_ 256
#define C_  32
#define O_  32
#define B_  8

#define ROWP 16896                    // ring slot pitch (258*64=16512 padded to 33*512)

// byte offsets into dynamic smem
#define BIAS_B 0
#define DWS_B  128
#define GS_B   1280
#define A_B    2560                   // 512B aligned; 3 ring slots
#define B_B    (A_B + 3*ROWP)         // 53248 (512-mult)
#define SPARE_B (B_B + 18*1024)       // 71680
#define SM_TOT_BYTES (SPARE_B + 2304) // 73984 -> 3 CTAs/SM

#define STG_STRIDE 36                 // epilogue staging o-stride (words)

// 512B-period XOR swizzle: bits {4,5} ^= bits {7,8}
#define SWZ(a) ((a) ^ ((((a) >> 7) & 3u) << 4))

// pre-packed, pre-swizzled B smem image (identical for every CTA)
__device__ uint32_t g_Bimg[4608];

__device__ __forceinline__ uint32_t smem_u32(const void* p) {
    uint32_t a;
    asm("{ .reg .u64 t; cvta.to.shared.u64 t, %1; cvt.u32.u64 %0, t; }" : "=r"(a) : "l"(p));
    return a;
}

__device__ __forceinline__ uint32_t pk2h(float a, float b) {
    __half2 h = __floats2half2_rn(a, b);
    return *reinterpret_cast<uint32_t*>(&h);
}

__device__ __forceinline__ void ldsm4(uint32_t& r0, uint32_t& r1, uint32_t& r2, uint32_t& r3,
                                      uint32_t addr) {
    asm volatile("ldmatrix.sync.aligned.m8n8.x4.shared.b16 {%0,%1,%2,%3}, [%4];"
                 : "=r"(r0), "=r"(r1), "=r"(r2), "=r"(r3) : "r"(addr));
}

__device__ __forceinline__ void mma16816(float* c, uint32_t a0, uint32_t a1,
                                         uint32_t a2, uint32_t a3,
                                         uint32_t b0, uint32_t b1) {
    asm volatile(
        "mma.sync.aligned.m16n8k16.row.col.f32.f16.f16.f32 "
        "{%0,%1,%2,%3}, {%4,%5,%6,%7}, {%8,%9}, {%0,%1,%2,%3};"
        : "+f"(c[0]), "+f"(c[1]), "+f"(c[2]), "+f"(c[3])
        : "r"(a0), "r"(a1), "r"(a2), "r"(a3), "r"(b0), "r"(b1));
}

// ---------------- prepack kernel: build swizzled B image once ----------------
__global__ void prepack_kernel(const float* __restrict__ weight)
{
    const int tid = threadIdx.x;   // 256 threads
    float wchunk[36];
    const float4* ws4 = (const float4*)(weight + tid * 36);
    #pragma unroll
    for (int j = 0; j < 9; j++) ((float4*)wchunk)[j] = ws4[j];
    const int o    = tid >> 3;
    const int kpg0 = (tid & 7) * 2;
    const int kch0 = kpg0 >> 3, kp0 = kpg0 & 7;
    const int kpg1 = kpg0 + 1;
    const int kch1 = kpg1 >> 3, kp1 = kpg1 & 7;
    #pragma unroll
    for (int tap = 0; tap < 9; tap++) {
        uint32_t rel0 = (uint32_t)(tap*2 + kch0)*1024 + o*32 + kp0*4;
        uint32_t rel1 = (uint32_t)(tap*2 + kch1)*1024 + o*32 + kp1*4;
        g_Bimg[SWZ(rel0) >> 2] = pk2h(wchunk[tap],      wchunk[tap + 9]);
        g_Bimg[SWZ(rel1) >> 2] = pk2h(wchunk[tap + 18], wchunk[tap + 27]);
    }
}

// ---------------- halo-row fill into ring slot ----------------
__device__ __forceinline__ void fill_row(char* smraw, const float* xb, int h, int tid)
{
    uint32_t sb = (uint32_t)A_B + ((uint32_t)(h + 1) % 3u) * ROWP;
    if ((unsigned)h < (unsigned)HW_) {
        const float* src = xb + (size_t)h * HW_ + tid;
        uint32_t rowoff = sb + (uint32_t)(tid + 1) * 64;
        #pragma unroll
        for (int q = 0; q < 4; q++) {
            float v[8];
            #pragma unroll
            for (int j = 0; j < 8; j++) v[j] = src[(size_t)(8*q + j) * (HW_*HW_)];
            uint4 w = make_uint4(pk2h(v[0], v[1]), pk2h(v[2], v[3]),
                                 pk2h(v[4], v[5]), pk2h(v[6], v[7]));
            *(uint4*)(smraw + SWZ(rowoff + q * 16)) = w;
        }
        if (tid < 8) {   // zero halo edge cols 0, 257
            int e = tid >> 2, q = tid & 3;
            uint32_t ro = sb + (uint32_t)(e * 257) * 64;
            *(uint4*)(smraw + SWZ(ro + q * 16)) = make_uint4(0, 0, 0, 0);
        }
    } else {
        uint4 z = make_uint4(0, 0, 0, 0);
        for (int j = tid; j < 1032; j += 256)
            *(uint4*)(smraw + sb + (uint32_t)j * 16) = z;
    }
}

// ---------------- main persistent kernel ----------------
__global__ __launch_bounds__(256, 3)
void dynamiconv_kernel(const float* __restrict__ x,
                       const float* __restrict__ dweight, const float* __restrict__ bias,
                       float* __restrict__ out)
{
    extern __shared__ char smraw[];
    float* bias_s = (float*)(smraw + BIAS_B);
    float* dws_s  = (float*)(smraw + DWS_B);
    float* gs     = (float*)(smraw + GS_B);

    const int tid  = threadIdx.x;
    const int lane = tid & 31;
    const int warp = tid >> 5;
    const int k = blockIdx.x;                 // 0..443
    const int nrows = (k < 272) ? 5 : 4;
    const int grow0 = (k < 272) ? 5 * k : 4 * k + 272;

    if (tid < 32) bias_s[tid] = bias[tid];
    for (int i = tid; i < 288; i += 256) dws_s[i] = dweight[i];

    // B fill once: linear copy of pre-swizzled image
    {
        const uint4* src = (const uint4*)g_Bimg;
        uint4* dst = (uint4*)(smraw + B_B);
        #pragma unroll
        for (int i = tid; i < 1152; i += 256) dst[i] = src[i];
    }

    const uint32_t sbase = smem_u32(smraw);
    const uint32_t laneArow = ((lane >> 3) & 1) * 8 + (lane & 7);
    const uint32_t laneAk   = (lane >> 4) * 16;
    const uint32_t laneBrow = ((lane >> 4) & 1) * 8 + (lane & 7);
    const uint32_t laneBk   = ((lane >> 3) & 1) * 16;
    const int pxw = warp * 32;
    const int tig = lane & 3, grp = lane >> 2;

    #pragma unroll 1
    for (int it = 0; it < nrows; it++) {
        const int g = grow0 + it;
        const int b = g >> 8;
        const int y = g & 255;
        const float* xb = x + (size_t)b * C_ * HW_ * HW_;

        if (it == 0 || y == 0) {
            fill_row(smraw, xb, y - 1, tid);
            fill_row(smraw, xb, y,     tid);
            fill_row(smraw, xb, y + 1, tid);
        } else {
            fill_row(smraw, xb, y + 1, tid);
        }
        __syncthreads();   // fill complete

        uint32_t ab0 = (uint32_t)A_B + ((uint32_t)y % 3u) * ROWP;
        uint32_t ab1 = (uint32_t)A_B + ((uint32_t)(y + 1) % 3u) * ROWP;
        uint32_t ab2 = (uint32_t)A_B + ((uint32_t)(y + 2) % 3u) * ROWP;

        // ---------- gate pass ----------
        {
            const int sh = (lane & 1) * 16;
            const uint32_t cw = (uint32_t)(lane >> 1) * 4;
            float dwr[9], sd2 = 0.f;
            #pragma unroll
            for (int j = 0; j < 9; j++) { dwr[j] = 0.5f * dws_s[lane * 9 + j]; sd2 += dwr[j]; }

            float c0[3], c1[3];
            #pragma unroll
            for (int r = 0; r < 3; r++) {
                uint32_t abr = (r == 0) ? ab0 : (r == 1) ? ab1 : ab2;
                uint32_t w0 = *(const uint32_t*)(smraw + SWZ(abr + (uint32_t)(pxw)     * 64 + cw));
                uint32_t w1 = *(const uint32_t*)(smraw + SWZ(abr + (uint32_t)(pxw + 1) * 64 + cw));
                float v0 = __half2float(__ushort_as_half((unsigned short)(w0 >> sh)));
                float v1 = __half2float(__ushort_as_half((unsigned short)(w1 >> sh)));
                asm("tanh.approx.f32 %0, %1;" : "=f"(c0[r]) : "f"(v0 * 0.5f));
                asm("tanh.approx.f32 %0, %1;" : "=f"(c1[r]) : "f"(v1 * 0.5f));
            }
            float v[16];
            #pragma unroll
            for (int px = 0; px < 32; px++) {
                float c2[3];
                #pragma unroll
                for (int r = 0; r < 3; r++) {
                    uint32_t abr = (r == 0) ? ab0 : (r == 1) ? ab1 : ab2;
                    uint32_t w = *(const uint32_t*)(smraw + SWZ(abr + (uint32_t)(pxw + px + 2) * 64 + cw));
                    float vv = __half2float(__ushort_as_half((unsigned short)(w >> sh)));
                    asm("tanh.approx.f32 %0, %1;" : "=f"(c2[r]) : "f"(vv * 0.5f));
                }
                float p = sd2;
                #pragma unroll
                for (int r = 0; r < 3; r++) {
                    p = fmaf(dwr[r * 3 + 0], c0[r], p);
                    p = fmaf(dwr[r * 3 + 1], c1[r], p);
                    p = fmaf(dwr[r * 3 + 2], c2[r], p);
                }
                v[px & 15] = p;
                #pragma unroll
                for (int r = 0; r < 3; r++) { c0[r] = c1[r]; c1[r] = c2[r]; }

                if ((px & 15) == 15) {
                    #pragma unroll
                    for (int i = 0; i < 16; i++)
                        v[i] += __shfl_xor_sync(0xFFFFFFFFu, v[i], 16);
                    #pragma unroll
                    for (int i = 0; i < 8; i++) {
                        float snd = (lane & 8) ? v[i] : v[i+8];
                        float kpv = (lane & 8) ? v[i+8] : v[i];
                        v[i] = kpv + __shfl_xor_sync(0xFFFFFFFFu, snd, 8);
                    }
                    #pragma unroll
                    for (int i = 0; i < 4; i++) {
                        float snd = (lane & 4) ? v[i] : v[i+4];
                        float kpv = (lane & 4) ? v[i+4] : v[i];
                        v[i] = kpv + __shfl_xor_sync(0xFFFFFFFFu, snd, 4);
                    }
                    #pragma unroll
                    for (int i = 0; i < 2; i++) {
                        float snd = (lane & 2) ? v[i] : v[i+2];
                        float kpv = (lane & 2) ? v[i+2] : v[i];
                        v[i] = kpv + __shfl_xor_sync(0xFFFFFFFFu, snd, 2);
                    }
                    {
                        float snd = (lane & 1) ? v[0] : v[1];
                        float kpv = (lane & 1) ? v[1] : v[0];
                        v[0] = kpv + __shfl_xor_sync(0xFFFFFFFFu, snd, 1);
                    }
                    if (lane < 16) gs[pxw + (px & ~15) + lane] = v[0];
                }
            }
        }

        // ---------- mainloop ----------
        float acc[2][4][4];
        #pragma unroll
        for (int mb = 0; mb < 2; mb++)
            #pragma unroll
            for (int nb = 0; nb < 4; nb++)
                #pragma unroll
                for (int r = 0; r < 4; r++) acc[mb][nb][r] = 0.0f;

        #pragma unroll 1
        for (int ki = 0; ki < 3; ki++) {
            uint32_t abk = (ki == 0) ? ab0 : (ki == 1) ? ab1 : ab2;
            #pragma unroll 1
            for (int kj = 0; kj < 3; kj++) {
                uint32_t araw = abk + (uint32_t)(pxw + kj + laneArow) * 64 + laneAk;
                // NOTE: SWZ is NOT additive over +32 (mask bits {4,5}); swizzle each
                // k-chunk base separately. +1024 (bit 10) IS carry-safe/additive.
                uint32_t sA0 = sbase + SWZ(araw);
                uint32_t sA1 = sbase + SWZ(araw + 32);
                uint32_t sB  = sbase + SWZ((uint32_t)B_B + (uint32_t)((ki*3 + kj) * 2) * 1024
                                           + laneBrow * 32 + laneBk);
                uint32_t a0[8], a1[8], b0q[8], b1q[8];
                ldsm4(a0[0], a0[1], a0[2], a0[3], sA0);
                ldsm4(a0[4], a0[5], a0[6], a0[7], sA0 + 1024);
                ldsm4(b0q[0], b0q[1], b0q[2], b0q[3], sB);
                ldsm4(b0q[4], b0q[5], b0q[6], b0q[7], sB + 512);
                ldsm4(a1[0], a1[1], a1[2], a1[3], sA1);
                ldsm4(a1[4], a1[5], a1[6], a1[7], sA1 + 1024);
                ldsm4(b1q[0], b1q[1], b1q[2], b1q[3], sB + 1024);
                ldsm4(b1q[4], b1q[5], b1q[6], b1q[7], sB + 1536);
                #pragma unroll
                for (int mb = 0; mb < 2; mb++) {
                    #pragma unroll
                    for (int nb = 0; nb < 4; nb++)
                        mma16816(acc[mb][nb], a0[mb*4+0], a0[mb*4+1], a0[mb*4+2], a0[mb*4+3],
                                 b0q[2*nb], b0q[2*nb+1]);
                    #pragma unroll
                    for (int nb = 0; nb < 4; nb++)
                        mma16816(acc[mb][nb], a1[mb*4+0], a1[mb*4+1], a1[mb*4+2], a1[mb*4+3],
                                 b1q[2*nb], b1q[2*nb+1]);
                }
            }
        }

        __syncthreads();   // all warps done reading ring before staging into dead slot

        // ---------- epilogue: 2 rounds of 16 o through dead-slot staging ----------
        {
            float* stw = (warp < 7)
                ? (float*)(smraw + ab0 + (uint32_t)warp * 2304)
                : (float*)(smraw + SPARE_B);
            float* ob = out + (size_t)b * O_ * HW_ * HW_ + (size_t)y * HW_ + pxw;
            const int gq = lane >> 3, iq = lane & 7;

            #pragma unroll
            for (int rd = 0; rd < 2; rd++) {
                #pragma unroll
                for (int mb = 0; mb < 2; mb++) {
                    int pxl = mb * 16 + grp;
                    float g0 = gs[pxw + pxl], g1 = gs[pxw + pxl + 8];
                    #pragma unroll
                    for (int nbl = 0; nbl < 2; nbl++) {
                        int nb = rd * 2 + nbl;
                        int ol = nbl * 8 + tig * 2;
                        int o  = rd * 16 + ol;
                        float bi0 = bias_s[o], bi1 = bias_s[o + 1];
                        stw[ol       * STG_STRIDE + pxl]     = fmaf(g0, acc[mb][nb][0], bi0);
                        stw[(ol + 1) * STG_STRIDE + pxl]     = fmaf(g0, acc[mb][nb][1], bi1);
                        stw[ol       * STG_STRIDE + pxl + 8] = fmaf(g1, acc[mb][nb][2], bi0);
                        stw[(ol + 1) * STG_STRIDE + pxl + 8] = fmaf(g1, acc[mb][nb][3], bi1);
                    }
                }
                __syncwarp();
                #pragma unroll
                for (int t = 0; t < 4; t++) {
                    int ol = t * 4 + gq;
                    int o  = rd * 16 + ol;
                    float4 vv = *(const float4*)(stw + ol * STG_STRIDE + iq * 4);
                    *(float4*)(ob + (size_t)o * (HW_*HW_) + iq * 4) = vv;
                }
                __syncwarp();
            }
        }

        __syncthreads();   // staging reads done before next fill overwrites dead slot
    }
}

extern "C" void kernel_launch(void* const* d_in, const int* in_sizes, int n_in,
                              void* d_out, int out_size)
{
    const float* x       = (const float*)d_in[0];
    const float* weight  = (const float*)d_in[1];
    const float* dweight = (const float*)d_in[2];
    const float* bias    = (const float*)d_in[3];
    float* out = (float*)d_out;

    cudaFuncSetAttribute(dynamiconv_kernel,
                         cudaFuncAttributeMaxDynamicSharedMemorySize, SM_TOT_BYTES);

    prepack_kernel<<<1, 256>>>(weight);

    dim3 grid(444, 1, 1);   // 3 x 148 SMs, one wave; rows 2048 = 272*5 + 172*4
    dynamiconv_kernel<<<grid, 256, SM_TOT_BYTES>>>(x, dweight, bias, out);
}

// round 16
// speedup vs baseline: 1.1894x; 1.0039x over previous
#include <cuda_runtime.h>
#include <cuda_fp16.h>
#include <cstdint>

#define HW_ 256
#define C_  32
#define O_  32
#define B_  8

#define ROWP 16896                    // ring slot pitch (258*64=16512 padded to 33*512)

// byte offsets into dynamic smem
#define BIAS_B 0
#define DWS_B  128
#define GS_B   1280
#define A_B    2560                   // 512B aligned; 3 ring slots
#define B_B    (A_B + 3*ROWP)         // 53248 (512-mult)
#define SPARE_B (B_B + 18*1024)       // 71680
#define SM_TOT_BYTES (SPARE_B + 2304) // 73984 -> 3 CTAs/SM

#define STG_STRIDE 36                 // epilogue staging o-stride (words)

// 512B-period XOR swizzle: bits {4,5} ^= bits {7,8}
#define SWZ(a) ((a) ^ ((((a) >> 7) & 3u) << 4))

// pre-packed, pre-swizzled B smem image (identical for every CTA)
__device__ uint32_t g_Bimg[4608];

__device__ __forceinline__ uint32_t smem_u32(const void* p) {
    uint32_t a;
    asm("{ .reg .u64 t; cvta.to.shared.u64 t, %1; cvt.u32.u64 %0, t; }" : "=r"(a) : "l"(p));
    return a;
}

__device__ __forceinline__ uint32_t pk2h(float a, float b) {
    __half2 h = __floats2half2_rn(a, b);
    return *reinterpret_cast<uint32_t*>(&h);
}

__device__ __forceinline__ void ldsm4(uint32_t& r0, uint32_t& r1, uint32_t& r2, uint32_t& r3,
                                      uint32_t addr) {
    asm volatile("ldmatrix.sync.aligned.m8n8.x4.shared.b16 {%0,%1,%2,%3}, [%4];"
                 : "=r"(r0), "=r"(r1), "=r"(r2), "=r"(r3) : "r"(addr));
}

__device__ __forceinline__ void mma16816(float* c, uint32_t a0, uint32_t a1,
                                         uint32_t a2, uint32_t a3,
                                         uint32_t b0, uint32_t b1) {
    asm volatile(
        "mma.sync.aligned.m16n8k16.row.col.f32.f16.f16.f32 "
        "{%0,%1,%2,%3}, {%4,%5,%6,%7}, {%8,%9}, {%0,%1,%2,%3};"
        : "+f"(c[0]), "+f"(c[1]), "+f"(c[2]), "+f"(c[3])
        : "r"(a0), "r"(a1), "r"(a2), "r"(a3), "r"(b0), "r"(b1));
}

// ---------------- prepack kernel: build swizzled B image once ----------------
__global__ void prepack_kernel(const float* __restrict__ weight)
{
    const int tid = threadIdx.x;   // 256 threads
    float wchunk[36];
    const float4* ws4 = (const float4*)(weight + tid * 36);
    #pragma unroll
    for (int j = 0; j < 9; j++) ((float4*)wchunk)[j] = ws4[j];
    const int o    = tid >> 3;
    const int kpg0 = (tid & 7) * 2;
    const int kch0 = kpg0 >> 3, kp0 = kpg0 & 7;
    const int kpg1 = kpg0 + 1;
    const int kch1 = kpg1 >> 3, kp1 = kpg1 & 7;
    #pragma unroll
    for (int tap = 0; tap < 9; tap++) {
        uint32_t rel0 = (uint32_t)(tap*2 + kch0)*1024 + o*32 + kp0*4;
        uint32_t rel1 = (uint32_t)(tap*2 + kch1)*1024 + o*32 + kp1*4;
        g_Bimg[SWZ(rel0) >> 2] = pk2h(wchunk[tap],      wchunk[tap + 9]);
        g_Bimg[SWZ(rel1) >> 2] = pk2h(wchunk[tap + 18], wchunk[tap + 27]);
    }
}

// ---------------- halo-row fill into ring slot ----------------
__device__ __forceinline__ void fill_row(char* smraw, const float* xb, int h, int tid)
{
    uint32_t sb = (uint32_t)A_B + ((uint32_t)(h + 1) % 3u) * ROWP;
    if ((unsigned)h < (unsigned)HW_) {
        const float* src = xb + (size_t)h * HW_ + tid;
        uint32_t rowoff = sb + (uint32_t)(tid + 1) * 64;
        #pragma unroll
        for (int q = 0; q < 4; q++) {
            float v[8];
            #pragma unroll
            for (int j = 0; j < 8; j++) v[j] = src[(size_t)(8*q + j) * (HW_*HW_)];
            uint4 w = make_uint4(pk2h(v[0], v[1]), pk2h(v[2], v[3]),
                                 pk2h(v[4], v[5]), pk2h(v[6], v[7]));
            *(uint4*)(smraw + SWZ(rowoff + q * 16)) = w;
        }
        if (tid < 8) {   // zero halo edge cols 0, 257
            int e = tid >> 2, q = tid & 3;
            uint32_t ro = sb + (uint32_t)(e * 257) * 64;
            *(uint4*)(smraw + SWZ(ro + q * 16)) = make_uint4(0, 0, 0, 0);
        }
    } else {
        uint4 z = make_uint4(0, 0, 0, 0);
        for (int j = tid; j < 1032; j += 256)
            *(uint4*)(smraw + sb + (uint32_t)j * 16) = z;
    }
}

// ---------------- main persistent kernel ----------------
__global__ __launch_bounds__(256, 3)
void dynamiconv_kernel(const float* __restrict__ x,
                       const float* __restrict__ dweight, const float* __restrict__ bias,
                       float* __restrict__ out)
{
    extern __shared__ char smraw[];
    float* bias_s = (float*)(smraw + BIAS_B);
    float* dws_s  = (float*)(smraw + DWS_B);
    float* gs     = (float*)(smraw + GS_B);

    const int tid  = threadIdx.x;
    const int lane = tid & 31;
    const int warp = tid >> 5;
    const int k = blockIdx.x;                 // 0..443
    const int nrows = (k < 272) ? 5 : 4;
    const int grow0 = (k < 272) ? 5 * k : 4 * k + 272;

    if (tid < 32) bias_s[tid] = bias[tid];
    for (int i = tid; i < 288; i += 256) dws_s[i] = dweight[i];

    // B fill once: linear copy of pre-swizzled image
    {
        const uint4* src = (const uint4*)g_Bimg;
        uint4* dst = (uint4*)(smraw + B_B);
        #pragma unroll
        for (int i = tid; i < 1152; i += 256) dst[i] = src[i];
    }

    const uint32_t sbase = smem_u32(smraw);
    const uint32_t laneArow = ((lane >> 3) & 1) * 8 + (lane & 7);
    const uint32_t laneAk   = (lane >> 4) * 16;
    const uint32_t laneBrow = ((lane >> 4) & 1) * 8 + (lane & 7);
    const uint32_t laneBk   = ((lane >> 3) & 1) * 16;
    const int pxw = warp * 32;
    const int tig = lane & 3, grp = lane >> 2;

    #pragma unroll 1
    for (int it = 0; it < nrows; it++) {
        const int g = grow0 + it;
        const int b = g >> 8;
        const int y = g & 255;
        const float* xb = x + (size_t)b * C_ * HW_ * HW_;

        if (it == 0 || y == 0) {
            fill_row(smraw, xb, y - 1, tid);
            fill_row(smraw, xb, y,     tid);
            fill_row(smraw, xb, y + 1, tid);
        } else {
            fill_row(smraw, xb, y + 1, tid);
        }
        __syncthreads();   // fill complete

        uint32_t ab0 = (uint32_t)A_B + ((uint32_t)y % 3u) * ROWP;
        uint32_t ab1 = (uint32_t)A_B + ((uint32_t)(y + 1) % 3u) * ROWP;
        uint32_t ab2 = (uint32_t)A_B + ((uint32_t)(y + 2) % 3u) * ROWP;

        // ---------- gate pass ----------
        {
            const int sh = (lane & 1) * 16;
            const uint32_t cw = (uint32_t)(lane >> 1) * 4;
            float dwr[9], sd2 = 0.f;
            #pragma unroll
            for (int j = 0; j < 9; j++) { dwr[j] = 0.5f * dws_s[lane * 9 + j]; sd2 += dwr[j]; }

            float c0[3], c1[3];
            #pragma unroll
            for (int r = 0; r < 3; r++) {
                uint32_t abr = (r == 0) ? ab0 : (r == 1) ? ab1 : ab2;
                uint32_t w0 = *(const uint32_t*)(smraw + SWZ(abr + (uint32_t)(pxw)     * 64 + cw));
                uint32_t w1 = *(const uint32_t*)(smraw + SWZ(abr + (uint32_t)(pxw + 1) * 64 + cw));
                float v0 = __half2float(__ushort_as_half((unsigned short)(w0 >> sh)));
                float v1 = __half2float(__ushort_as_half((unsigned short)(w1 >> sh)));
                asm("tanh.approx.f32 %0, %1;" : "=f"(c0[r]) : "f"(v0 * 0.5f));
                asm("tanh.approx.f32 %0, %1;" : "=f"(c1[r]) : "f"(v1 * 0.5f));
            }
            float v[16];
            #pragma unroll
            for (int px = 0; px < 32; px++) {
                float c2[3];
                #pragma unroll
                for (int r = 0; r < 3; r++) {
                    uint32_t abr = (r == 0) ? ab0 : (r == 1) ? ab1 : ab2;
                    uint32_t w = *(const uint32_t*)(smraw + SWZ(abr + (uint32_t)(pxw + px + 2) * 64 + cw));
                    float vv = __half2float(__ushort_as_half((unsigned short)(w >> sh)));
                    asm("tanh.approx.f32 %0, %1;" : "=f"(c2[r]) : "f"(vv * 0.5f));
                }
                float p = sd2;
                #pragma unroll
                for (int r = 0; r < 3; r++) {
                    p = fmaf(dwr[r * 3 + 0], c0[r], p);
                    p = fmaf(dwr[r * 3 + 1], c1[r], p);
                    p = fmaf(dwr[r * 3 + 2], c2[r], p);
                }
                v[px & 15] = p;
                #pragma unroll
                for (int r = 0; r < 3; r++) { c0[r] = c1[r]; c1[r] = c2[r]; }

                if ((px & 15) == 15) {
                    #pragma unroll
                    for (int i = 0; i < 16; i++)
                        v[i] += __shfl_xor_sync(0xFFFFFFFFu, v[i], 16);
                    #pragma unroll
                    for (int i = 0; i < 8; i++) {
                        float snd = (lane & 8) ? v[i] : v[i+8];
                        float kpv = (lane & 8) ? v[i+8] : v[i];
                        v[i] = kpv + __shfl_xor_sync(0xFFFFFFFFu, snd, 8);
                    }
                    #pragma unroll
                    for (int i = 0; i < 4; i++) {
                        float snd = (lane & 4) ? v[i] : v[i+4];
                        float kpv = (lane & 4) ? v[i+4] : v[i];
                        v[i] = kpv + __shfl_xor_sync(0xFFFFFFFFu, snd, 4);
                    }
                    #pragma unroll
                    for (int i = 0; i < 2; i++) {
                        float snd = (lane & 2) ? v[i] : v[i+2];
                        float kpv = (lane & 2) ? v[i+2] : v[i];
                        v[i] = kpv + __shfl_xor_sync(0xFFFFFFFFu, snd, 2);
                    }
                    {
                        float snd = (lane & 1) ? v[0] : v[1];
                        float kpv = (lane & 1) ? v[1] : v[0];
                        v[0] = kpv + __shfl_xor_sync(0xFFFFFFFFu, snd, 1);
                    }
                    if (lane < 16) gs[pxw + (px & ~15) + lane] = v[0];
                }
            }
        }

        // ---------- mainloop ----------
        float acc[2][4][4];
        #pragma unroll
        for (int mb = 0; mb < 2; mb++)
            #pragma unroll
            for (int nb = 0; nb < 4; nb++)
                #pragma unroll
                for (int r = 0; r < 4; r++) acc[mb][nb][r] = 0.0f;

        #pragma unroll 1
        for (int ki = 0; ki < 3; ki++) {
            uint32_t abk = (ki == 0) ? ab0 : (ki == 1) ? ab1 : ab2;
            #pragma unroll 1
            for (int kj = 0; kj < 3; kj++) {
                uint32_t araw = abk + (uint32_t)(pxw + kj + laneArow) * 64 + laneAk;
                // NOTE: SWZ is NOT additive over +32 (mask bits {4,5}); swizzle each
                // k-chunk base separately. +1024 (bit 10) IS carry-safe/additive.
                uint32_t sA0 = sbase + SWZ(araw);
                uint32_t sA1 = sbase + SWZ(araw + 32);
                uint32_t sB  = sbase + SWZ((uint32_t)B_B + (uint32_t)((ki*3 + kj) * 2) * 1024
                                           + laneBrow * 32 + laneBk);
                uint32_t a0[8], a1[8], b0q[8], b1q[8];
                ldsm4(a0[0], a0[1], a0[2], a0[3], sA0);
                ldsm4(a0[4], a0[5], a0[6], a0[7], sA0 + 1024);
                ldsm4(b0q[0], b0q[1], b0q[2], b0q[3], sB);
                ldsm4(b0q[4], b0q[5], b0q[6], b0q[7], sB + 512);
                ldsm4(a1[0], a1[1], a1[2], a1[3], sA1);
                ldsm4(a1[4], a1[5], a1[6], a1[7], sA1 + 1024);
                ldsm4(b1q[0], b1q[1], b1q[2], b1q[3], sB + 1024);
                ldsm4(b1q[4], b1q[5], b1q[6], b1q[7], sB + 1536);
                #pragma unroll
                for (int mb = 0; mb < 2; mb++) {
                    #pragma unroll
                    for (int nb = 0; nb < 4; nb++)
                        mma16816(acc[mb][nb], a0[mb*4+0], a0[mb*4+1], a0[mb*4+2], a0[mb*4+3],
                                 b0q[2*nb], b0q[2*nb+1]);
                    #pragma unroll
                    for (int nb = 0; nb < 4; nb++)
                        mma16816(acc[mb][nb], a1[mb*4+0], a1[mb*4+1], a1[mb*4+2], a1[mb*4+3],
                                 b1q[2*nb], b1q[2*nb+1]);
                }
            }
        }

        __syncthreads();   // all warps done reading ring before staging into dead slot

        // ---------- epilogue: 2 rounds of 16 o through dead-slot staging ----------
        {
            float* stw = (warp < 7)
                ? (float*)(smraw + ab0 + (uint32_t)warp * 2304)
                : (float*)(smraw + SPARE_B);
            float* ob = out + (size_t)b * O_ * HW_ * HW_ + (size_t)y * HW_ + pxw;
            const int gq = lane >> 3, iq = lane & 7;

            #pragma unroll
            for (int rd = 0; rd < 2; rd++) {
                #pragma unroll
                for (int mb = 0; mb < 2; mb++) {
                    int pxl = mb * 16 + grp;
                    float g0 = gs[pxw + pxl], g1 = gs[pxw + pxl + 8];
                    #pragma unroll
                    for (int nbl = 0; nbl < 2; nbl++) {
                        int nb = rd * 2 + nbl;
                        int ol = nbl * 8 + tig * 2;
                        int o  = rd * 16 + ol;
                        float bi0 = bias_s[o], bi1 = bias_s[o + 1];
                        stw[ol       * STG_STRIDE + pxl]     = fmaf(g0, acc[mb][nb][0], bi0);
                        stw[(ol + 1) * STG_STRIDE + pxl]     = fmaf(g0, acc[mb][nb][1], bi1);
                        stw[ol       * STG_STRIDE + pxl + 8] = fmaf(g1, acc[mb][nb][2], bi0);
                        stw[(ol + 1) * STG_STRIDE + pxl + 8] = fmaf(g1, acc[mb][nb][3], bi1);
                    }
                }
                __syncwarp();
                #pragma unroll
                for (int t = 0; t < 4; t++) {
                    int ol = t * 4 + gq;
                    int o  = rd * 16 + ol;
                    float4 vv = *(const float4*)(stw + ol * STG_STRIDE + iq * 4);
                    *(float4*)(ob + (size_t)o * (HW_*HW_) + iq * 4) = vv;
                }
                __syncwarp();
            }
        }

        __syncthreads();   // staging reads done before next fill overwrites dead slot
    }
}

extern "C" void kernel_launch(void* const* d_in, const int* in_sizes, int n_in,
                              void* d_out, int out_size)
{
    const float* x       = (const float*)d_in[0];
    const float* weight  = (const float*)d_in[1];
    const float* dweight = (const float*)d_in[2];
    const float* bias    = (const float*)d_in[3];
    float* out = (float*)d_out;

    cudaFuncSetAttribute(dynamiconv_kernel,
                         cudaFuncAttributeMaxDynamicSharedMemorySize, SM_TOT_BYTES);

    prepack_kernel<<<1, 256>>>(weight);

    dim3 grid(444, 1, 1);   // 3 x 148 SMs, one wave; rows 2048 = 272*5 + 172*4
    dynamiconv_kernel<<<grid, 256, SM_TOT_BYTES>>>(x, dweight, bias, out);
}